// round 3
// baseline (speedup 1.0000x reference)
#include <cuda_runtime.h>
#include <math.h>
#include <stdint.h>

#define N_NODES 2000
#define NFEAT   128
#define LB      128
#define TFEAT   36
#define FC1     256
#define DELTA_MIN 0.05f

// ---------------- scratch (device globals; no allocation) ----------------
__device__ float g_accP[25][FC1 * LB];     // split-K partials, [split][t*256 + k]
__device__ float g_HsT[FC1 * LB];          // relu spatial hidden, [k][t]
__device__ float g_HtT[FC1 * LB];          // relu temporal hidden, [k][t]
__device__ float g_U1[N_NODES * LB];       // U[:,:,i1]  [n][t]  (tf32-rounded)
__device__ float g_P [N_NODES * LB];       // U2 @ B^T   [m][f]  (tf32-rounded)

__device__ __forceinline__ float to_tf32(float x) {
    uint32_t u;
    asm("cvt.rna.tf32.f32 %0, %1;" : "=r"(u) : "f"(x));
    return __uint_as_float(u);
}

// ---------------- kernel 1: spatial hidden, split-K, coalesced ------------
// grid (8 k-tiles of 32, 25 j-splits of 80), block 256
__global__ __launch_bounds__(256) void k_hid_s(const float* __restrict__ li,
                                               const float* __restrict__ Ws1) {
    __shared__ float smA[16 * 132];   // [jj][t], pad 132
    __shared__ float smW[16 * 36];    // [jj][kk], pad 36
    const int k0 = blockIdx.x * 32;
    const int j0 = blockIdx.y * 80;
    const int tid = threadIdx.x;
    const int tx = tid & 7;           // k-group (4 cols each -> 32)
    const int ty = tid >> 3;          // t-group (4 rows each -> 128)

    float acc[4][4];
#pragma unroll
    for (int u = 0; u < 4; u++)
#pragma unroll
        for (int v = 0; v < 4; v++) acc[u][v] = 0.f;

    for (int jb = 0; jb < 80; jb += 16) {
        __syncthreads();
#pragma unroll
        for (int it = 0; it < 8; it++) {
            int e = tid + it * 256;
            int t = e >> 4, jj = e & 15;
            smA[jj * 132 + t] = li[t * N_NODES + j0 + jb + jj];
        }
#pragma unroll
        for (int it = 0; it < 2; it++) {
            int e = tid + it * 256;
            int jj = e >> 5, kk = e & 31;
            smW[jj * 36 + kk] = Ws1[(j0 + jb + jj) * FC1 + k0 + kk];
        }
        __syncthreads();
#pragma unroll
        for (int jj = 0; jj < 16; jj++) {
            float4 a = *(const float4*)&smA[jj * 132 + ty * 4];
            float4 w = *(const float4*)&smW[jj * 36 + tx * 4];
            float av[4] = {a.x, a.y, a.z, a.w};
            float wv[4] = {w.x, w.y, w.z, w.w};
#pragma unroll
            for (int u = 0; u < 4; u++)
#pragma unroll
                for (int v = 0; v < 4; v++) acc[u][v] += av[u] * wv[v];
        }
    }
    const int sp = blockIdx.y;
#pragma unroll
    for (int u = 0; u < 4; u++) {
        int t = ty * 4 + u;
        float4 v = make_float4(acc[u][0], acc[u][1], acc[u][2], acc[u][3]);
        *(float4*)&g_accP[sp][t * FC1 + k0 + tx * 4] = v;
    }
}

// ---------------- kernel 2: finalize spatial + temporal hidden ------------
// grid 128 (t), block 256 (k)
__global__ void k_hid_fin(const float* __restrict__ tf, const float* __restrict__ Wt1,
                          const float* __restrict__ bs1, const float* __restrict__ bt1) {
    const int t = blockIdx.x;
    const int k = threadIdx.x;
    __shared__ float stf[TFEAT];
    if (k < TFEAT) stf[k] = tf[t * TFEAT + k];

    float hs = bs1[k];
#pragma unroll
    for (int s = 0; s < 25; s++) hs += g_accP[s][t * FC1 + k];
    g_HsT[k * 128 + t] = fmaxf(hs, 0.f);

    __syncthreads();
    float a = bt1[k];
#pragma unroll
    for (int j = 0; j < TFEAT; j++)
        a += stf[j] * Wt1[j * FC1 + k];
    g_HtT[k * 128 + t] = fmaxf(a, 0.f);
}

// ---------------- kernel 3: embed (gathered cols) + fused P = U2 @ B^T ----
// grid 250 (8 nodes each), block 256
__global__ __launch_bounds__(256) void k_embed(
    const float* __restrict__ Ws2, const float* __restrict__ bs2,
    const float* __restrict__ Wt2, const float* __restrict__ bt2,
    const float* __restrict__ B,
    const int* __restrict__ idxp, const int* __restrict__ tdp) {

    __shared__ float smWs[256 * 16];   // [k][col]
    __shared__ float smWt[256 * 16];
    __shared__ float smU2[8 * 132];    // [m_local][t]
    __shared__ float smB[32 * 129];    // [g][f]
    __shared__ float smBs[16], smBt[16];

    const int idx = idxp[0];
    const int td  = tdp[0];
    const int i1  = (td >= 0) ? (idx - td) : idx;
    const int i2  = (td >= 0) ? idx        : (idx + td);

    const int n0  = blockIdx.x * 8;
    const int tid = threadIdx.x;

    for (int e = tid; e < 256 * 16; e += 256) {
        int k = e >> 4, cc = e & 15;
        int n = n0 + (cc >> 1);
        int c = n * NFEAT + ((cc & 1) ? i2 : i1);
        smWs[e] = Ws2[(long)k * (N_NODES * NFEAT) + c];
        smWt[e] = Wt2[(long)k * (N_NODES * NFEAT) + c];
    }
    if (tid < 16) {
        int n = n0 + (tid >> 1);
        int c = n * NFEAT + ((tid & 1) ? i2 : i1);
        smBs[tid] = bs2[c];
        smBt[tid] = bt2[c];
    }
    __syncthreads();

    const int t = tid & 127;
    const int h = tid >> 7;   // cols h*8 .. h*8+7

    float accS[8], accT[8];
#pragma unroll
    for (int i = 0; i < 8; i++) { accS[i] = 0.f; accT[i] = 0.f; }

    for (int k = 0; k < 256; k++) {
        float hs = g_HsT[k * 128 + t];
        float ht = g_HtT[k * 128 + t];
        float4 a0 = *(const float4*)&smWs[k * 16 + h * 8];
        float4 a1 = *(const float4*)&smWs[k * 16 + h * 8 + 4];
        float4 b0 = *(const float4*)&smWt[k * 16 + h * 8];
        float4 b1 = *(const float4*)&smWt[k * 16 + h * 8 + 4];
        accS[0] += hs * a0.x; accS[1] += hs * a0.y; accS[2] += hs * a0.z; accS[3] += hs * a0.w;
        accS[4] += hs * a1.x; accS[5] += hs * a1.y; accS[6] += hs * a1.z; accS[7] += hs * a1.w;
        accT[0] += ht * b0.x; accT[1] += ht * b0.y; accT[2] += ht * b0.z; accT[3] += ht * b0.w;
        accT[4] += ht * b1.x; accT[5] += ht * b1.y; accT[6] += ht * b1.z; accT[7] += ht * b1.w;
    }

#pragma unroll
    for (int i = 0; i < 8; i++) {
        int col = h * 8 + i;
        float v = fmaxf(accS[i] + smBs[col], 0.f) + fmaxf(accT[i] + smBt[col], 0.f);
        int n = n0 + (col >> 1);
        if (col & 1) smU2[(col >> 1) * 132 + t] = v;       // full precision -> P
        else         g_U1[n * 128 + t] = to_tf32(v);       // tf32 -> mma A
    }
    __syncthreads();

    // ---- fused P = U2 @ B^T for this block's 8 nodes ----
    const int f  = tid & 127;
    const int mh = tid >> 7;          // m-half: nodes mh*4 .. mh*4+3
    float pacc[4];
#pragma unroll
    for (int q = 0; q < 4; q++) pacc[q] = 0.f;

    for (int gc = 0; gc < 128; gc += 32) {
        __syncthreads();
        // stage B chunk transposed: smB[g][f] <- B[f][gc+g], conflict-free stores
#pragma unroll
        for (int it = 0; it < 4; it++) {
            int e = tid + it * 256;
            int fr = e >> 3, g4 = (e & 7) * 4;
            float4 b = *(const float4*)&B[fr * 128 + gc + g4];
            smB[(g4 + 0) * 129 + fr] = b.x;
            smB[(g4 + 1) * 129 + fr] = b.y;
            smB[(g4 + 2) * 129 + fr] = b.z;
            smB[(g4 + 3) * 129 + fr] = b.w;
        }
        __syncthreads();
#pragma unroll
        for (int g = 0; g < 32; g++) {
            float bv = smB[g * 129 + f];
#pragma unroll
            for (int q = 0; q < 4; q++)
                pacc[q] += smU2[(mh * 4 + q) * 132 + gc + g] * bv;
        }
    }
#pragma unroll
    for (int q = 0; q < 4; q++)
        g_P[(n0 + mh * 4 + q) * 128 + f] = to_tf32(pacc[q]);
}

// ---------------- kernel 4: x = U1 @ P^T (tf32 tensor cores, pipelined) ---
#define MMA_TF32(c, a, b)                                                          \
    asm volatile("mma.sync.aligned.m16n8k8.row.col.f32.tf32.tf32.f32 "             \
                 "{%0,%1,%2,%3},{%4,%5,%6,%7},{%8,%9},{%0,%1,%2,%3};"              \
                 : "+f"(c[0]), "+f"(c[1]), "+f"(c[2]), "+f"(c[3])                  \
                 : "r"(a[0]), "r"(a[1]), "r"(a[2]), "r"(a[3]), "r"(b[0]), "r"(b[1]))

__global__ __launch_bounds__(256) void k_gemm(float* __restrict__ out) {
    __shared__ float smA[128 * 36];   // [n][k-chunk 32], pad 36
    __shared__ float smB[128 * 36];   // [m][k-chunk 32], pad 36
    const int n0 = blockIdx.y * 128;
    const int m0 = blockIdx.x * 128;
    const int tid = threadIdx.x;
    const int warp = tid >> 5, lane = tid & 31;
    const int wn = warp & 3;          // n-strip of 32
    const int wm = warp >> 2;         // m-strip of 64
    const int g = lane >> 2, tg = lane & 3;
    const int lrow = tid >> 3, lkk = (tid & 7) * 4;   // load coords (row, 4 k)

    float acc[2][8][4];
#pragma unroll
    for (int i = 0; i < 2; i++)
#pragma unroll
        for (int j = 0; j < 8; j++)
#pragma unroll
            for (int q = 0; q < 4; q++) acc[i][j][q] = 0.f;

    float4 ra[4], rb[4];
    // prefetch chunk 0
#pragma unroll
    for (int it = 0; it < 4; it++) {
        int row = lrow + it * 32;
        ra[it] = (n0 + row < N_NODES) ? *(const float4*)&g_U1[(n0 + row) * 128 + lkk]
                                      : make_float4(0, 0, 0, 0);
        rb[it] = (m0 + row < N_NODES) ? *(const float4*)&g_P [(m0 + row) * 128 + lkk]
                                      : make_float4(0, 0, 0, 0);
    }

    for (int kc = 0; kc < 4; kc++) {
        __syncthreads();
#pragma unroll
        for (int it = 0; it < 4; it++) {
            int row = lrow + it * 32;
            *(float4*)&smA[row * 36 + lkk] = ra[it];
            *(float4*)&smB[row * 36 + lkk] = rb[it];
        }
        __syncthreads();
        if (kc < 3) {
            int kn = (kc + 1) * 32;
#pragma unroll
            for (int it = 0; it < 4; it++) {
                int row = lrow + it * 32;
                ra[it] = (n0 + row < N_NODES) ? *(const float4*)&g_U1[(n0 + row) * 128 + kn + lkk]
                                              : make_float4(0, 0, 0, 0);
                rb[it] = (m0 + row < N_NODES) ? *(const float4*)&g_P [(m0 + row) * 128 + kn + lkk]
                                              : make_float4(0, 0, 0, 0);
            }
        }
#pragma unroll
        for (int ks = 0; ks < 4; ks++) {
            int k0 = ks * 8;
            uint32_t af[2][4];
#pragma unroll
            for (int i = 0; i < 2; i++) {
                int base = (wn * 32 + i * 16) * 36 + k0;
                af[i][0] = __float_as_uint(smA[base + g * 36 + tg]);
                af[i][1] = __float_as_uint(smA[base + (g + 8) * 36 + tg]);
                af[i][2] = __float_as_uint(smA[base + g * 36 + tg + 4]);
                af[i][3] = __float_as_uint(smA[base + (g + 8) * 36 + tg + 4]);
            }
            uint32_t bf[8][2];
#pragma unroll
            for (int j = 0; j < 8; j++) {
                int bb = (wm * 64 + j * 8 + g) * 36 + k0 + tg;
                bf[j][0] = __float_as_uint(smB[bb]);
                bf[j][1] = __float_as_uint(smB[bb + 4]);
            }
#pragma unroll
            for (int i = 0; i < 2; i++)
#pragma unroll
                for (int j = 0; j < 8; j++)
                    MMA_TF32(acc[i][j], af[i], bf[j]);
        }
    }

    // epilogue: threshold + store
#pragma unroll
    for (int i = 0; i < 2; i++) {
#pragma unroll
        for (int j = 0; j < 8; j++) {
            int n = n0 + wn * 32 + i * 16 + g;
            int m = m0 + wm * 64 + j * 8 + 2 * tg;
            if (m < N_NODES) {
                float2 v0, v1;
                v0.x = (acc[i][j][0] >= DELTA_MIN) ? acc[i][j][0] : 0.f;
                v0.y = (acc[i][j][1] >= DELTA_MIN) ? acc[i][j][1] : 0.f;
                v1.x = (acc[i][j][2] >= DELTA_MIN) ? acc[i][j][2] : 0.f;
                v1.y = (acc[i][j][3] >= DELTA_MIN) ? acc[i][j][3] : 0.f;
                if (n < N_NODES)     *(float2*)&out[(long)n * N_NODES + m] = v0;
                if (n + 8 < N_NODES) *(float2*)&out[(long)(n + 8) * N_NODES + m] = v1;
            }
        }
    }
}

// ---------------- kernel 5: in-place row softmax (float4) -----------------
// grid 2000, block 256 (threads 0..249 active, 8 elems each)
__global__ void k_softmax(float* __restrict__ out) {
    const int row = blockIdx.x;
    float* p = out + (long)row * N_NODES;
    const int tid = threadIdx.x;
    const bool act = tid < 250;
    __shared__ float redM[8];
    __shared__ float redS[8];

    float4 v0, v1;
    float mx = -1e30f;
    if (act) {
        v0 = *(const float4*)&p[tid * 8];
        v1 = *(const float4*)&p[tid * 8 + 4];
        mx = fmaxf(fmaxf(fmaxf(v0.x, v0.y), fmaxf(v0.z, v0.w)),
                   fmaxf(fmaxf(v1.x, v1.y), fmaxf(v1.z, v1.w)));
    }
#pragma unroll
    for (int o = 16; o; o >>= 1) mx = fmaxf(mx, __shfl_xor_sync(0xFFFFFFFFu, mx, o));
    if ((tid & 31) == 0) redM[tid >> 5] = mx;
    __syncthreads();
    float gmax = redM[0];
#pragma unroll
    for (int w = 1; w < 8; w++) gmax = fmaxf(gmax, redM[w]);

    float s = 0.f;
    if (act) {
        v0.x = __expf(v0.x - gmax); v0.y = __expf(v0.y - gmax);
        v0.z = __expf(v0.z - gmax); v0.w = __expf(v0.w - gmax);
        v1.x = __expf(v1.x - gmax); v1.y = __expf(v1.y - gmax);
        v1.z = __expf(v1.z - gmax); v1.w = __expf(v1.w - gmax);
        s = v0.x + v0.y + v0.z + v0.w + v1.x + v1.y + v1.z + v1.w;
    }
#pragma unroll
    for (int o = 16; o; o >>= 1) s += __shfl_xor_sync(0xFFFFFFFFu, s, o);
    if ((tid & 31) == 0) redS[tid >> 5] = s;
    __syncthreads();
    float tot = 0.f;
#pragma unroll
    for (int w = 0; w < 8; w++) tot += redS[w];
    float inv = 1.f / tot;
    if (act) {
        v0.x *= inv; v0.y *= inv; v0.z *= inv; v0.w *= inv;
        v1.x *= inv; v1.y *= inv; v1.z *= inv; v1.w *= inv;
        *(float4*)&p[tid * 8]     = v0;
        *(float4*)&p[tid * 8 + 4] = v1;
    }
}

// ---------------- launch ---------------------------------------------------
extern "C" void kernel_launch(void* const* d_in, const int* in_sizes, int n_in,
                              void* d_out, int out_size) {
    const float* tf   = (const float*)d_in[0];
    const float* li   = (const float*)d_in[1];
    const float* Ws1  = (const float*)d_in[2];
    const float* bs1  = (const float*)d_in[3];
    const float* Ws2  = (const float*)d_in[4];
    const float* bs2  = (const float*)d_in[5];
    const float* Wt1  = (const float*)d_in[6];
    const float* bt1  = (const float*)d_in[7];
    const float* Wt2  = (const float*)d_in[8];
    const float* bt2  = (const float*)d_in[9];
    const float* B    = (const float*)d_in[10];
    const int*   idxp = (const int*)d_in[11];
    const int*   tdp  = (const int*)d_in[12];
    float* out = (float*)d_out;

    k_hid_s  <<<dim3(8, 25), 256>>>(li, Ws1);
    k_hid_fin<<<128, 256>>>(tf, Wt1, bs1, bt1);
    k_embed  <<<250, 256>>>(Ws2, bs2, Wt2, bt2, B, idxp, tdp);
    k_gemm   <<<dim3(16, 16), 256>>>(out);
    k_softmax<<<2000, 256>>>(out);
}